// round 5
// baseline (speedup 1.0000x reference)
#include <cuda_runtime.h>
#include <cstdint>

// MaskLayer: per-(batch,channel) spatial argmax -> L1-distance mask -> scale.
// x, out: [B, 14, 14, 512] float32, channel-innermost.
//
// Persistent-CTA version: grid = #SMs, 1 CTA/SM, 256 threads, two 100KB smem
// buffers. Each CTA loops over (batch, 128-channel) tiles with a depth-2
// cp.async pipeline: prefetch tile t+1 while reducing + masked-storing tile t.
// DRAM load stream never stalls on the phase barriers.

static constexpr int IMGS     = 14;
static constexpr int SPATIAL  = IMGS * IMGS;              // 196
static constexpr int DEPTH    = 512;
static constexpr int DTILE    = 128;
static constexpr int BLOCK    = 256;
static constexpr int TILE_FLOATS = SPATIAL * DTILE;       // 25088
static constexpr int TILE_VEC4   = TILE_FLOATS / 4;       // 6272
static constexpr int LDITERS  = (TILE_VEC4 + BLOCK - 1) / BLOCK;   // 25 (last half-active)
static constexpr int SMEM_BYTES = 2 * TILE_FLOATS * (int)sizeof(float);  // 200704

static constexpr float NEG_BIG = -3.402823466e38f;

__device__ __forceinline__ uint32_t smem_u32(const void* p) {
    return (uint32_t)__cvta_generic_to_shared(p);
}

// Stage one (batch, dtile) tile into smem via cp.async.cg (16B, L1-bypass).
// Per-warp each iteration covers 512 contiguous gmem bytes; smem conflict-free.
__device__ __forceinline__ void prefetch_tile(const float* __restrict__ x,
                                              int tt, float* dst, int tid) {
    const int b  = tt >> 2;                 // DEPTH / DTILE = 4 tiles per batch
    const int dt = tt & 3;
    const float* __restrict__ src = x + (size_t)b * (SPATIAL * DEPTH) + dt * DTILE;
#pragma unroll
    for (int k = 0; k < LDITERS; k++) {
        int idx = tid + k * BLOCK;
        if (idx < TILE_VEC4) {              // warp-uniform predicate (k=24: warps 0-3)
            int s  = idx >> 5;              // 32 float4 per spatial position
            int c4 = (idx & 31) << 2;
            uint32_t d = smem_u32(dst + s * DTILE + c4);
            const float* g = src + (size_t)s * DEPTH + c4;
            asm volatile("cp.async.cg.shared.global [%0], [%1], 16;\n"
                         :: "r"(d), "l"(g));
        }
    }
    asm volatile("cp.async.commit_group;\n" ::: "memory");
}

__global__ void __launch_bounds__(BLOCK, 1)
mask_layer_kernel(const float* __restrict__ x, float* __restrict__ out, int ntiles) {
    extern __shared__ float smem[];         // 2 x [SPATIAL][DTILE]
    __shared__ int sidx[DTILE];             // packed (row | col<<16) per channel

    const int tid = threadIdx.x;
    int tt = (int)blockIdx.x;
    if (tt >= ntiles) return;               // block-uniform

    prefetch_tile(x, tt, smem, tid);        // prime buffer 0

    const float TAUF = 0.5f / 196.0f;               // TAU
    const float TC   = TAUF * (4.0f / 14.0f);       // TAU * BETA / IMG_SIZE

    int parity = 0;
    for (; tt < ntiles; tt += (int)gridDim.x) {
        float* cur = smem + parity * TILE_FLOATS;
        int nxt = tt + (int)gridDim.x;
        if (nxt < ntiles) {
            // Issue next tile's loads BEFORE waiting on current tile: the
            // DRAM stream stays saturated through the compute phases below.
            prefetch_tile(x, nxt, smem + (parity ^ 1) * TILE_FLOATS, tid);
            asm volatile("cp.async.wait_group 1;\n" ::: "memory");
        } else {
            asm volatile("cp.async.wait_group 0;\n" ::: "memory");
        }
        __syncthreads();

        // ---- Phase B: per-channel argmax(rowmax) / argmax(colmax) ----
        // 256 threads / 128 channels: both halves redundantly compute the
        // same channel (c = tid & 127) -> conflict-free LDS, no combine.
        // Strict '>' with ascending index == jnp.argmax first-occurrence.
        {
            const int c = tid & (DTILE - 1);
            float colmax[IMGS];
#pragma unroll
            for (int j = 0; j < IMGS; j++) colmax[j] = NEG_BIG;

            float bestRow = NEG_BIG;
            int rowIdx = 0;
#pragma unroll 2
            for (int i = 0; i < IMGS; i++) {
                float rmax = NEG_BIG;
#pragma unroll
                for (int j = 0; j < IMGS; j++) {
                    float v = cur[(i * IMGS + j) * DTILE + c];
                    rmax = fmaxf(rmax, v);
                    colmax[j] = fmaxf(colmax[j], v);
                }
                if (rmax > bestRow) { bestRow = rmax; rowIdx = i; }
            }
            int colIdx = 0;
            float bestCol = colmax[0];
#pragma unroll
            for (int j = 1; j < IMGS; j++)
                if (colmax[j] > bestCol) { bestCol = colmax[j]; colIdx = j; }

            if (tid < DTILE) sidx[c] = rowIdx | (colIdx << 16);
        }
        __syncthreads();

        // ---- Phase C: apply mask, streaming 16B stores ----
        {
            const int b  = tt >> 2;
            const int dt = tt & 3;
            float* __restrict__ dstg = out + (size_t)b * (SPATIAL * DEPTH) + dt * DTILE;
#pragma unroll
            for (int k = 0; k < LDITERS; k++) {
                int idx = tid + k * BLOCK;
                if (idx < TILE_VEC4) {
                    int s  = idx >> 5;
                    int c4 = (idx & 31) << 2;
                    int i  = s / IMGS;
                    int j  = s - i * IMGS;

                    float4 v = *(const float4*)(cur + s * DTILE + c4);
                    int4   p = *(const int4*)(sidx + c4);

                    // mask = TAU * max(1 - COEF*l1, -1) = max(TAU - TAU*COEF*l1, -TAU)
                    auto msk = [&](int pk) -> float {
                        int r  = pk & 0xFFFF;
                        int cc = pk >> 16;
                        int l1 = abs(i - r) + abs(j - cc);
                        return fmaxf(fmaf((float)l1, -TC, TAUF), -TAUF);
                    };

                    float4 o;
                    o.x = msk(p.x) * v.x;
                    o.y = msk(p.y) * v.y;
                    o.z = msk(p.z) * v.z;
                    o.w = msk(p.w) * v.w;
                    __stcs((float4*)(dstg + (size_t)s * DEPTH + c4), o);  // evict-first
                }
            }
        }
        __syncthreads();        // all reads of 'cur' done before it is re-filled
        parity ^= 1;
    }
}

extern "C" void kernel_launch(void* const* d_in, const int* in_sizes, int n_in,
                              void* d_out, int out_size) {
    (void)n_in; (void)out_size;
    const float* x = (const float*)d_in[0];
    float* out = (float*)d_out;

    int n = in_sizes[0];                                  // B * 196 * 512
    int batches = n / (SPATIAL * DEPTH);                  // 1024
    int ntiles  = batches * (DEPTH / DTILE);              // 4096

    int dev = 0, sms = 148;
    cudaGetDevice(&dev);
    cudaDeviceGetAttribute(&sms, cudaDevAttrMultiProcessorCount, dev);
    int grid = sms < ntiles ? sms : ntiles;

    // Host-side attribute calls: immediate, deterministic, capture-safe.
    cudaFuncSetAttribute(mask_layer_kernel,
                         cudaFuncAttributeMaxDynamicSharedMemorySize, SMEM_BYTES);

    mask_layer_kernel<<<grid, BLOCK, SMEM_BYTES>>>(x, out, ntiles);
}

// round 6
// speedup vs baseline: 1.2002x; 1.2002x over previous
#include <cuda_runtime.h>
#include <cstdint>

// MaskLayer: per-(batch,channel) spatial argmax -> L1-distance mask -> scale.
// x, out: [B, 14, 14, 512] float32, channel-innermost.
//
// R5: back to the R3 one-shot-CTA structure (it beat the explicit pipeline),
// but with DTILE=64 -> 50KB smem/CTA -> 4 CTAs/SM (reg-capped via
// __launch_bounds__(128,4)). Four independent CTAs per SM in uncorrelated
// load/reduce/store phases keep both the HBM read and write streams busy.

static constexpr int IMGS     = 14;
static constexpr int SPATIAL  = IMGS * IMGS;              // 196
static constexpr int DEPTH    = 512;
static constexpr int DTILE    = 64;                       // channels per CTA
static constexpr int BLOCK    = 128;
static constexpr int TILE_FLOATS = SPATIAL * DTILE;       // 12544
static constexpr int TILE_VEC4   = TILE_FLOATS / 4;       // 3136
static constexpr int ITERS    = (TILE_VEC4 + BLOCK - 1) / BLOCK;  // 25 (last: warps 0-1)
static constexpr int SMEM_BYTES = TILE_FLOATS * (int)sizeof(float);  // 50176

static constexpr float NEG_BIG = -3.402823466e38f;

__device__ __forceinline__ uint32_t smem_u32(const void* p) {
    return (uint32_t)__cvta_generic_to_shared(p);
}

__global__ void __launch_bounds__(BLOCK, 4)
mask_layer_kernel(const float* __restrict__ x, float* __restrict__ out) {
    extern __shared__ float tile[];        // [SPATIAL][DTILE]
    __shared__ int sidx[DTILE];            // packed (row | col<<16) per channel

    const int tid = threadIdx.x;
    const int dt  = blockIdx.x & 7;        // DEPTH / DTILE = 8 tiles per batch
    const int b   = blockIdx.x >> 3;
    const size_t base = (size_t)b * (SPATIAL * DEPTH) + (size_t)dt * DTILE;
    const float* __restrict__ src = x + base;

    // ---- Phase A: stage tile via cp.async.cg (16B, L1-bypass) ----
    // idx -> (s = idx>>4 spatial, c4 = (idx&15)*4 channel). Each spatial
    // position is 256B contiguous in gmem; a warp covers 2 positions (512B).
#pragma unroll
    for (int k = 0; k < ITERS; k++) {
        int idx = tid + k * BLOCK;
        if (idx < TILE_VEC4) {             // warp-uniform (k=24: warps 0-1 only)
            int s  = idx >> 4;
            int c4 = (idx & 15) << 2;
            uint32_t d = smem_u32(tile + s * DTILE + c4);
            const float* g = src + (size_t)s * DEPTH + c4;
            asm volatile("cp.async.cg.shared.global [%0], [%1], 16;\n"
                         :: "r"(d), "l"(g));
        }
    }
    asm volatile("cp.async.commit_group;\ncp.async.wait_group 0;\n" ::: "memory");
    __syncthreads();

    // ---- Phase B: per-channel argmax(rowmax) / argmax(colmax) ----
    // 128 threads / 64 channels: both halves redundantly compute channel
    // c = tid & 63 (conflict-free LDS, no combine needed).
    // Strict '>' with ascending index == jnp.argmax first-occurrence.
    {
        const int c = tid & (DTILE - 1);
        float colmax[IMGS];
#pragma unroll
        for (int j = 0; j < IMGS; j++) colmax[j] = NEG_BIG;

        float bestRow = NEG_BIG;
        int rowIdx = 0;
#pragma unroll 2
        for (int i = 0; i < IMGS; i++) {
            float rmax = NEG_BIG;
#pragma unroll
            for (int j = 0; j < IMGS; j++) {
                float v = tile[(i * IMGS + j) * DTILE + c];
                rmax = fmaxf(rmax, v);
                colmax[j] = fmaxf(colmax[j], v);
            }
            if (rmax > bestRow) { bestRow = rmax; rowIdx = i; }
        }
        int colIdx = 0;
        float bestCol = colmax[0];
#pragma unroll
        for (int j = 1; j < IMGS; j++)
            if (colmax[j] > bestCol) { bestCol = colmax[j]; colIdx = j; }

        if (tid < DTILE) sidx[c] = rowIdx | (colIdx << 16);
    }
    __syncthreads();

    // ---- Phase C: apply mask, vectorized 16B stores ----
    const float TAUF = 0.5f / 196.0f;               // TAU
    const float TC   = TAUF * (4.0f / 14.0f);       // TAU * BETA / IMG_SIZE
    float* __restrict__ dstg = out + base;

#pragma unroll 5
    for (int k = 0; k < ITERS; k++) {
        int idx = tid + k * BLOCK;
        if (idx < TILE_VEC4) {
            int s  = idx >> 4;
            int c4 = (idx & 15) << 2;
            int i  = s / IMGS;
            int j  = s - i * IMGS;

            float4 v = *(const float4*)(tile + s * DTILE + c4);
            int4   p = *(const int4*)(sidx + c4);

            // mask = TAU*max(1 - COEF*l1, -1) = max(TAU - (TAU*COEF)*l1, -TAU)
            auto msk = [&](int pk) -> float {
                int r  = pk & 0xFFFF;
                int cc = pk >> 16;
                int l1 = abs(i - r) + abs(j - cc);
                return fmaxf(fmaf((float)l1, -TC, TAUF), -TAUF);
            };

            float4 o;
            o.x = msk(p.x) * v.x;
            o.y = msk(p.y) * v.y;
            o.z = msk(p.z) * v.z;
            o.w = msk(p.w) * v.w;
            *(float4*)(dstg + (size_t)s * DEPTH + c4) = o;
        }
    }
}

extern "C" void kernel_launch(void* const* d_in, const int* in_sizes, int n_in,
                              void* d_out, int out_size) {
    (void)n_in; (void)out_size;
    const float* x = (const float*)d_in[0];
    float* out = (float*)d_out;

    int n = in_sizes[0];                                  // B * 196 * 512
    int batches = n / (SPATIAL * DEPTH);                  // 1024
    int grid = batches * (DEPTH / DTILE);                 // 8192

    // Host-side attribute call: immediate, deterministic, capture-safe.
    cudaFuncSetAttribute(mask_layer_kernel,
                         cudaFuncAttributeMaxDynamicSharedMemorySize, SMEM_BYTES);

    mask_layer_kernel<<<grid, BLOCK, SMEM_BYTES>>>(x, out);
}